// round 5
// baseline (speedup 1.0000x reference)
#include <cuda_runtime.h>
#include <cuda_bf16.h>
#include <math.h>
#include <stdint.h>

// ---------------------------------------------------------------------------
#define T_TOK 16384
#define DLAT  1024
#define NEXP  4
#define RLORA 16
#define NLAYER 3

#define BM 128
#define BN 256
#define BK 32
#define KITERS (DLAT / BK)            // 32
#define PITCH_B 80                    // bytes per smem row (40 bf16), conflict-free
#define STAGE_ROWS 768                // Ah128 | Al128 | Wh256 | Wl256
#define STAGE_BYTES (STAGE_ROWS * PITCH_B)   // 61440
#define NSTAGE 3
#define SMEM_TOTAL (NSTAGE * STAGE_BYTES)    // 184320

#define MODE_S 0
#define MODE_Y 1

#define TDSZ ((size_t)T_TOK * DLAT)

// ---------------------------------------------------------------------------
// Scratch
// ---------------------------------------------------------------------------
__device__ __nv_bfloat16 g_acth[4 * T_TOK * DLAT];   // slots: 0=enc x,1=enc s,2=tgt x,3=tgt s
__device__ __nv_bfloat16 g_actl[4 * T_TOK * DLAT];
__device__ __nv_bfloat16 g_WhT[12 * DLAT * DLAT];    // [slot][N][K]
__device__ __nv_bfloat16 g_WlT[12 * DLAT * DLAT];
__device__ float g_bufX[2 * T_TOK * DLAT];           // fp32 x per stack
__device__ float g_bufY[2 * T_TOK * DLAT];           // pre-LN y per stack
__device__ float g_h[T_TOK * NEXP * RLORA];
__device__ float g_mask[T_TOK * NEXP];

// ---------------------------------------------------------------------------
// PTX helpers (base sm_80-era features only)
// ---------------------------------------------------------------------------
__device__ __forceinline__ uint32_t smem_to_u32(const void* p) {
    uint32_t a;
    asm("{ .reg .u64 t; cvta.to.shared.u64 t, %1; cvt.u32.u64 %0, t; }" : "=r"(a) : "l"(p));
    return a;
}

__device__ __forceinline__ void cp16(uint32_t dst, const void* src) {
    asm volatile("cp.async.cg.shared.global [%0], [%1], 16;" :: "r"(dst), "l"(src));
}

#define CP_COMMIT() asm volatile("cp.async.commit_group;" ::: "memory")
#define CP_WAIT1()  asm volatile("cp.async.wait_group 1;" ::: "memory")

#define LDSM4(r0, r1, r2, r3, addr) \
    asm volatile("ldmatrix.sync.aligned.m8n8.x4.shared.b16 {%0,%1,%2,%3}, [%4];" \
                 : "=r"(r0), "=r"(r1), "=r"(r2), "=r"(r3) : "r"(addr))

__device__ __forceinline__ void hmma(float* d, const uint32_t* a, const uint32_t* b) {
    asm volatile(
        "mma.sync.aligned.m16n8k16.row.col.f32.bf16.bf16.f32 "
        "{%0,%1,%2,%3}, {%4,%5,%6,%7}, {%8,%9}, {%0,%1,%2,%3};"
        : "+f"(d[0]), "+f"(d[1]), "+f"(d[2]), "+f"(d[3])
        : "r"(a[0]), "r"(a[1]), "r"(a[2]), "r"(a[3]), "r"(b[0]), "r"(b[1]));
}

// ---------------------------------------------------------------------------
// Batched bf16-split HMMA GEMM (gridDim.z = 2 stacks)
// acc = Ah*Wh + Ah*Wl + Al*Wh  (Markidis 3-term)
// MODE_S: s = sigmoid(acc+bias)*X*td -> bf16 hi/lo into act slot 1+2z
// MODE_Y: y = acc + bias + X         -> fp32 Cf (+ z*TDSZ)
// ---------------------------------------------------------------------------
template <int MODE>
__global__ __launch_bounds__(256)
void hgemm(const __nv_bfloat16* __restrict__ AhB, const __nv_bfloat16* __restrict__ AlB,
           const __nv_bfloat16* __restrict__ WhB, const __nv_bfloat16* __restrict__ WlB,
           int as0, int ws0, int ws1,
           const float* __restrict__ b0, const float* __restrict__ b1,
           const float* __restrict__ t0, const float* __restrict__ t1,
           const float* __restrict__ X0, const float* __restrict__ X1,
           float* __restrict__ CfB,
           __nv_bfloat16* __restrict__ ChB, __nv_bfloat16* __restrict__ ClB)
{
    extern __shared__ char smem[];
    const uint32_t sb = smem_to_u32(smem);
    const int tid = threadIdx.x;
    const int wid = tid >> 5;
    const int lane = tid & 31;
    const int wm = wid >> 2;        // 0..1 -> M 64-tiles
    const int wn = wid & 3;         // 0..3 -> N 64-tiles
    const int m0 = blockIdx.y * BM;
    const int n0 = blockIdx.x * BN;
    const int z  = blockIdx.z;

    const size_t aoff = (size_t)(as0 + 2 * z) * TDSZ;
    const size_t woff = (size_t)(z ? ws1 : ws0) * DLAT * DLAT;
    const float* bias = z ? b1 : b0;
    const float* td   = z ? t1 : t0;
    const float* X    = z ? X1 : X0;

    // cp.async: 3 uniform row streams per thread (row, row+256, row+512)
    const __nv_bfloat16* s1 = (tid < 128)
        ? (AhB + aoff + (size_t)(m0 + tid) * DLAT)
        : (AlB + aoff + (size_t)(m0 + tid - 128) * DLAT);
    const __nv_bfloat16* s2 = WhB + woff + (size_t)(n0 + tid) * DLAT;
    const __nv_bfloat16* s3 = WlB + woff + (size_t)(n0 + tid) * DLAT;
    const uint32_t d1 = sb + tid * PITCH_B;
    const uint32_t d2 = sb + (tid + 256) * PITCH_B;
    const uint32_t d3 = sb + (tid + 512) * PITCH_B;

    const int a_row = (lane & 7) + ((lane >> 3) & 1) * 8;
    const int a_k   = ((lane >> 4) & 1) * 8;
    const int b_row = (lane & 7) + ((lane >> 4) & 1) * 8;
    const int b_k   = ((lane >> 3) & 1) * 8;

    float acc[4][8][4];
#pragma unroll
    for (int i = 0; i < 4; i++)
#pragma unroll
        for (int j = 0; j < 8; j++)
#pragma unroll
            for (int q = 0; q < 4; q++) acc[i][j][q] = 0.f;

#pragma unroll
    for (int s = 0; s < 2; s++) {
        const int k0 = s * BK;
        const uint32_t so = s * STAGE_BYTES;
#pragma unroll
        for (int j = 0; j < 4; j++) {
            cp16(d1 + so + j * 16, s1 + k0 + j * 8);
            cp16(d2 + so + j * 16, s2 + k0 + j * 8);
            cp16(d3 + so + j * 16, s3 + k0 + j * 8);
        }
        CP_COMMIT();
    }

    for (int it = 0; it < KITERS; it++) {
        CP_WAIT1();
        __syncthreads();
        const int pf = it + 2;
        if (pf < KITERS) {
            const int k0 = pf * BK;
            const uint32_t so = (pf % NSTAGE) * STAGE_BYTES;
#pragma unroll
            for (int j = 0; j < 4; j++) {
                cp16(d1 + so + j * 16, s1 + k0 + j * 8);
                cp16(d2 + so + j * 16, s2 + k0 + j * 8);
                cp16(d3 + so + j * 16, s3 + k0 + j * 8);
            }
        }
        CP_COMMIT();

        const uint32_t st = sb + (it % NSTAGE) * STAGE_BYTES;
#pragma unroll
        for (int ko = 0; ko < BK; ko += 16) {
            uint32_t ah[4][4], al[4][4];
#pragma unroll
            for (int mi = 0; mi < 4; mi++) {
                const uint32_t ra = st + (uint32_t)(wm * 64 + mi * 16 + a_row) * PITCH_B
                                       + (uint32_t)(ko + a_k) * 2;
                LDSM4(ah[mi][0], ah[mi][1], ah[mi][2], ah[mi][3], ra);
                LDSM4(al[mi][0], al[mi][1], al[mi][2], al[mi][3], ra + 128 * PITCH_B);
            }
#pragma unroll
            for (int half = 0; half < 2; half++) {
                uint32_t bh[4][2], bl[4][2];
#pragma unroll
                for (int lnp = 0; lnp < 2; lnp++) {
                    const int np = half * 2 + lnp;
                    const uint32_t rb = st + (uint32_t)(256 + wn * 64 + np * 16 + b_row) * PITCH_B
                                           + (uint32_t)(ko + b_k) * 2;
                    uint32_t q0, q1, q2, q3;
                    LDSM4(q0, q1, q2, q3, rb);
                    bh[2 * lnp][0] = q0; bh[2 * lnp][1] = q1;
                    bh[2 * lnp + 1][0] = q2; bh[2 * lnp + 1][1] = q3;
                    LDSM4(q0, q1, q2, q3, rb + 256 * PITCH_B);
                    bl[2 * lnp][0] = q0; bl[2 * lnp][1] = q1;
                    bl[2 * lnp + 1][0] = q2; bl[2 * lnp + 1][1] = q3;
                }
#pragma unroll
                for (int mi = 0; mi < 4; mi++)
#pragma unroll
                    for (int bi = 0; bi < 4; bi++) {
                        float* d = acc[mi][half * 4 + bi];
                        hmma(d, ah[mi], bh[bi]);
                        hmma(d, ah[mi], bl[bi]);
                        hmma(d, al[mi], bh[bi]);
                    }
            }
        }
    }

    // ---------------- epilogue ----------------
    __nv_bfloat16* Ch = ChB + (size_t)(1 + 2 * z) * TDSZ;
    __nv_bfloat16* Cl = ClB + (size_t)(1 + 2 * z) * TDSZ;
    float* Cf = CfB + (size_t)z * TDSZ;

    const int qr = lane >> 2;
    const int qc = (lane & 3) * 2;
#pragma unroll
    for (int mi = 0; mi < 4; mi++) {
#pragma unroll
        for (int ni = 0; ni < 8; ni++) {
            const int r = m0 + wm * 64 + mi * 16 + qr;
            const int c = n0 + wn * 64 + ni * 8 + qc;
            const float* d = acc[mi][ni];
#pragma unroll
            for (int h = 0; h < 2; h++) {
                const int rr = r + h * 8;
                const float v0 = d[2 * h], v1 = d[2 * h + 1];
                const float2 xv = *(const float2*)&X[(size_t)rr * DLAT + c];
                const float2 bv = *(const float2*)&bias[c];
                if (MODE == MODE_S) {
                    const float2 tv = *(const float2*)&td[c];
                    const float s0 = (1.f / (1.f + expf(-(v0 + bv.x)))) * xv.x * tv.x;
                    const float s1v = (1.f / (1.f + expf(-(v1 + bv.y)))) * xv.y * tv.y;
                    const __nv_bfloat16 h0 = __float2bfloat16(s0);
                    const __nv_bfloat16 h1 = __float2bfloat16(s1v);
                    const __nv_bfloat16 l0 = __float2bfloat16(s0 - __bfloat162float(h0));
                    const __nv_bfloat16 l1 = __float2bfloat16(s1v - __bfloat162float(h1));
                    *(__nv_bfloat162*)&Ch[(size_t)rr * DLAT + c] = __nv_bfloat162(h0, h1);
                    *(__nv_bfloat162*)&Cl[(size_t)rr * DLAT + c] = __nv_bfloat162(l0, l1);
                } else {
                    float2 o;
                    o.x = v0 + bv.x + xv.x;
                    o.y = v1 + bv.y + xv.y;
                    *(float2*)&Cf[(size_t)rr * DLAT + c] = o;
                }
            }
        }
    }
}

// ---------------------------------------------------------------------------
// Weight transpose + bf16 split
// ---------------------------------------------------------------------------
__global__ void wsplit_kernel(const float* __restrict__ W, int slot_base, int slot_stride,
                              __nv_bfloat16* __restrict__ WhT, __nv_bfloat16* __restrict__ WlT)
{
    __shared__ float t[32][33];
    const int l = blockIdx.z;
    const float* Wl = W + (size_t)l * DLAT * DLAT;
    const int bx = blockIdx.x * 32;
    const int by = blockIdx.y * 32;
    const int tx = threadIdx.x, ty = threadIdx.y;
#pragma unroll
    for (int i = 0; i < 32; i += 8)
        t[ty + i][tx] = Wl[(size_t)(by + ty + i) * DLAT + bx + tx];
    __syncthreads();
    const size_t slot = (size_t)(slot_base + l * slot_stride) * DLAT * DLAT;
#pragma unroll
    for (int i = 0; i < 32; i += 8) {
        const float v = t[tx][ty + i];
        const __nv_bfloat16 h = __float2bfloat16(v);
        const size_t o = slot + (size_t)(bx + ty + i) * DLAT + by + tx;
        WhT[o] = h;
        WlT[o] = __float2bfloat16(v - __bfloat162float(h));
    }
}

// ---------------------------------------------------------------------------
// Activation split
// ---------------------------------------------------------------------------
__global__ void asplit_kernel(const float* __restrict__ x,
                              __nv_bfloat16* __restrict__ oh, __nv_bfloat16* __restrict__ ol)
{
    const int i = blockIdx.x * blockDim.x + threadIdx.x;
    const float4 v = ((const float4*)x)[i];
    __nv_bfloat16 h0 = __float2bfloat16(v.x), h1 = __float2bfloat16(v.y);
    __nv_bfloat16 h2 = __float2bfloat16(v.z), h3 = __float2bfloat16(v.w);
    __nv_bfloat162* oh2 = (__nv_bfloat162*)oh;
    __nv_bfloat162* ol2 = (__nv_bfloat162*)ol;
    oh2[2 * i]     = __nv_bfloat162(h0, h1);
    oh2[2 * i + 1] = __nv_bfloat162(h2, h3);
    ol2[2 * i]     = __nv_bfloat162(__float2bfloat16(v.x - __bfloat162float(h0)),
                                    __float2bfloat16(v.y - __bfloat162float(h1)));
    ol2[2 * i + 1] = __nv_bfloat162(__float2bfloat16(v.z - __bfloat162float(h2)),
                                    __float2bfloat16(v.w - __bfloat162float(h3)));
}

// ---------------------------------------------------------------------------
// Batched LayerNorm (gridDim.y = stack); optional bf16 hi/lo split output
// ---------------------------------------------------------------------------
__global__ void ln_kernel(const float* __restrict__ Yb,
                          const float* __restrict__ g0, const float* __restrict__ g1,
                          const float* __restrict__ be0, const float* __restrict__ be1,
                          float* __restrict__ out0, float* __restrict__ out1,
                          __nv_bfloat16* __restrict__ ohB, __nv_bfloat16* __restrict__ olB,
                          int split)
{
    __shared__ float sh[18];
    const int row = blockIdx.x;
    const int z   = blockIdx.y;
    const int tid = threadIdx.x;
    const float* yr = Yb + (size_t)z * TDSZ + (size_t)row * DLAT;
    const float* g  = z ? g1 : g0;
    const float* b  = z ? be1 : be0;
    float* out = z ? out1 : out0;

    float4 v = *(const float4*)&yr[tid * 4];
    float s = v.x + v.y + v.z + v.w;
#pragma unroll
    for (int o = 16; o; o >>= 1) s += __shfl_xor_sync(0xffffffffu, s, o);
    if ((tid & 31) == 0) sh[tid >> 5] = s;
    __syncthreads();
    if (tid == 0) {
        float t = 0.f;
        for (int i = 0; i < 8; i++) t += sh[i];
        sh[16] = t * (1.0f / 1024.0f);
    }
    __syncthreads();
    const float mu = sh[16];
    const float dx = v.x - mu, dy = v.y - mu, dz = v.z - mu, dw = v.w - mu;
    float q = dx * dx + dy * dy + dz * dz + dw * dw;
#pragma unroll
    for (int o = 16; o; o >>= 1) q += __shfl_xor_sync(0xffffffffu, q, o);
    if ((tid & 31) == 0) sh[8 + (tid >> 5)] = q;
    __syncthreads();
    if (tid == 0) {
        float t = 0.f;
        for (int i = 0; i < 8; i++) t += sh[8 + i];
        sh[17] = rsqrtf(t * (1.0f / 1024.0f) + 1e-5f);
    }
    __syncthreads();
    const float r = sh[17];

    float4 gv = *(const float4*)&g[tid * 4];
    float4 bv = *(const float4*)&b[tid * 4];
    float4 o4;
    o4.x = dx * r * gv.x + bv.x;
    o4.y = dy * r * gv.y + bv.y;
    o4.z = dz * r * gv.z + bv.z;
    o4.w = dw * r * gv.w + bv.w;
    *(float4*)&out[(size_t)row * DLAT + tid * 4] = o4;

    if (split) {
        __nv_bfloat16* oh = ohB + (size_t)(2 * z) * TDSZ;
        __nv_bfloat16* ol = olB + (size_t)(2 * z) * TDSZ;
        const size_t o = (size_t)row * DLAT + tid * 4;
        __nv_bfloat16 h0 = __float2bfloat16(o4.x), h1 = __float2bfloat16(o4.y);
        __nv_bfloat16 h2 = __float2bfloat16(o4.z), h3 = __float2bfloat16(o4.w);
        *(__nv_bfloat162*)&oh[o]     = __nv_bfloat162(h0, h1);
        *(__nv_bfloat162*)&oh[o + 2] = __nv_bfloat162(h2, h3);
        *(__nv_bfloat162*)&ol[o]     = __nv_bfloat162(__float2bfloat16(o4.x - __bfloat162float(h0)),
                                                      __float2bfloat16(o4.y - __bfloat162float(h1)));
        *(__nv_bfloat162*)&ol[o + 2] = __nv_bfloat162(__float2bfloat16(o4.z - __bfloat162float(h2)),
                                                      __float2bfloat16(o4.w - __bfloat162float(h3)));
    }
}

// ---------------------------------------------------------------------------
// Gate: softmax + top-2 mask
// ---------------------------------------------------------------------------
__global__ void gate_kernel(const float* __restrict__ Z, const float* __restrict__ gw,
                            const float* __restrict__ gb,
                            float* __restrict__ probs_out, float* __restrict__ mask_out)
{
    const int warp = (blockIdx.x * blockDim.x + threadIdx.x) >> 5;
    const int lane = threadIdx.x & 31;
    if (warp >= T_TOK) return;

    float a0 = 0.f, a1 = 0.f, a2 = 0.f, a3 = 0.f;
    const float* zr = Z + (size_t)warp * DLAT;
    for (int d = lane; d < DLAT; d += 32) {
        const float z = zr[d];
        float4 w = *(const float4*)&gw[d * 4];
        a0 = fmaf(z, w.x, a0); a1 = fmaf(z, w.y, a1);
        a2 = fmaf(z, w.z, a2); a3 = fmaf(z, w.w, a3);
    }
#pragma unroll
    for (int o = 16; o; o >>= 1) {
        a0 += __shfl_xor_sync(0xffffffffu, a0, o);
        a1 += __shfl_xor_sync(0xffffffffu, a1, o);
        a2 += __shfl_xor_sync(0xffffffffu, a2, o);
        a3 += __shfl_xor_sync(0xffffffffu, a3, o);
    }
    if (lane == 0) {
        float lg[4] = {a0 + gb[0], a1 + gb[1], a2 + gb[2], a3 + gb[3]};
        float mx = lg[0];
        for (int i = 1; i < 4; i++) mx = fmaxf(mx, lg[i]);
        float p[4], sum = 0.f;
        for (int i = 0; i < 4; i++) { p[i] = expf(lg[i] - mx); sum += p[i]; }
        const float inv = 1.f / sum;
        for (int i = 0; i < 4; i++) p[i] *= inv;
        int i1 = 0;
        for (int i = 1; i < 4; i++) if (p[i] > p[i1]) i1 = i;
        int i2 = -1;
        for (int i = 0; i < 4; i++)
            if (i != i1 && (i2 < 0 || p[i] > p[i2])) i2 = i;
        for (int i = 0; i < 4; i++) {
            probs_out[(size_t)warp * 4 + i] = p[i];
            mask_out[(size_t)warp * 4 + i] = (i == i1 || i == i2) ? 1.f : 0.f;
        }
    }
}

// ---------------------------------------------------------------------------
// MoLE up-proj (SIMT)
// ---------------------------------------------------------------------------
__global__ __launch_bounds__(256)
void mole_h_kernel(const float* __restrict__ Z, const float* __restrict__ lora_A,
                   const float* __restrict__ mask, float* __restrict__ H)
{
    __shared__ float As[16][132];
    __shared__ float Ws[16][64];
    const int tid = threadIdx.x;
    const int m0 = blockIdx.x * 128;
    const int trow = tid >> 4;
    const int tcol = tid & 15;

    float acc[8][4];
#pragma unroll
    for (int i = 0; i < 8; i++)
#pragma unroll
        for (int j = 0; j < 4; j++) acc[i][j] = 0.f;

    const int ar = tid >> 2;
    const int ac4 = tid & 3;

    for (int k0 = 0; k0 < 1024; k0 += 16) {
#pragma unroll
        for (int i = 0; i < 2; i++) {
            const int r = ar + i * 64;
            float4 v = *(const float4*)&Z[(size_t)(m0 + r) * 1024 + k0 + ac4 * 4];
            As[ac4 * 4 + 0][r] = v.x; As[ac4 * 4 + 1][r] = v.y;
            As[ac4 * 4 + 2][r] = v.z; As[ac4 * 4 + 3][r] = v.w;
        }
#pragma unroll
        for (int i = 0; i < 4; i++) {
            const int lin = tid + 256 * i;
            const int k = lin >> 6, n = lin & 63;
            Ws[k][n] = lora_A[(size_t)(n >> 4) * (1024 * 16) + (size_t)(k0 + k) * 16 + (n & 15)];
        }
        __syncthreads();
#pragma unroll
        for (int kk = 0; kk < 16; kk++) {
            float4 a0 = *(const float4*)&As[kk][trow * 8];
            float4 a1 = *(const float4*)&As[kk][trow * 8 + 4];
            float4 b0 = *(const float4*)&Ws[kk][tcol * 4];
            float a[8] = {a0.x, a0.y, a0.z, a0.w, a1.x, a1.y, a1.z, a1.w};
            float b[4] = {b0.x, b0.y, b0.z, b0.w};
#pragma unroll
            for (int i = 0; i < 8; i++)
#pragma unroll
                for (int j = 0; j < 4; j++)
                    acc[i][j] = fmaf(a[i], b[j], acc[i][j]);
        }
        __syncthreads();
    }
#pragma unroll
    for (int i = 0; i < 8; i++) {
        const int m = m0 + trow * 8 + i;
#pragma unroll
        for (int j = 0; j < 4; j++) {
            const int n = tcol * 4 + j;
            const float x = acc[i][j];
            const float hv = 0.5f * x * (1.f + erff(x * 0.70710678118654752f));
            H[(size_t)m * 64 + n] = hv * mask[(size_t)m * 4 + (n >> 4)];
        }
    }
}

// ---------------------------------------------------------------------------
// MoLE down-proj (SIMT)
// ---------------------------------------------------------------------------
__global__ __launch_bounds__(256)
void mole_p_kernel(const float* __restrict__ A, const float* __restrict__ W,
                   float* __restrict__ C)
{
    const int N = 1024;
    __shared__ float As[16][132];
    __shared__ float Ws[16][128];
    const int tid = threadIdx.x;
    const int m0 = blockIdx.y * 128;
    const int n0 = blockIdx.x * 128;
    const int trow = tid >> 4;
    const int tcol = tid & 15;

    float acc[8][8];
#pragma unroll
    for (int i = 0; i < 8; i++)
#pragma unroll
        for (int j = 0; j < 8; j++) acc[i][j] = 0.f;

    const int ar = tid >> 2;
    const int ac4 = tid & 3;
    const int wr = tid >> 5;
    const int wc4 = tid & 31;

    for (int k0 = 0; k0 < 64; k0 += 16) {
#pragma unroll
        for (int i = 0; i < 2; i++) {
            const int r = ar + i * 64;
            float4 v = *(const float4*)&A[(size_t)(m0 + r) * 64 + k0 + ac4 * 4];
            As[ac4 * 4 + 0][r] = v.x; As[ac4 * 4 + 1][r] = v.y;
            As[ac4 * 4 + 2][r] = v.z; As[ac4 * 4 + 3][r] = v.w;
        }
#pragma unroll
        for (int i = 0; i < 2; i++) {
            const int r = wr + i * 8;
            float4 v = *(const float4*)&W[(size_t)(k0 + r) * N + n0 + wc4 * 4];
            *(float4*)&Ws[r][wc4 * 4] = v;
        }
        __syncthreads();
#pragma unroll
        for (int kk = 0; kk < 16; kk++) {
            float4 a0 = *(const float4*)&As[kk][trow * 8];
            float4 a1 = *(const float4*)&As[kk][trow * 8 + 4];
            float4 b0 = *(const float4*)&Ws[kk][tcol * 8];
            float4 b1 = *(const float4*)&Ws[kk][tcol * 8 + 4];
            float a[8] = {a0.x, a0.y, a0.z, a0.w, a1.x, a1.y, a1.z, a1.w};
            float b[8] = {b0.x, b0.y, b0.z, b0.w, b1.x, b1.y, b1.z, b1.w};
#pragma unroll
            for (int i = 0; i < 8; i++)
#pragma unroll
                for (int j = 0; j < 8; j++)
                    acc[i][j] = fmaf(a[i], b[j], acc[i][j]);
        }
        __syncthreads();
    }
#pragma unroll
    for (int i = 0; i < 8; i++) {
        const int m = m0 + trow * 8 + i;
#pragma unroll
        for (int j = 0; j < 8; j++)
            C[(size_t)m * N + tcol * 8 + n0 + j] = acc[i][j];
    }
}

// ---------------------------------------------------------------------------
// Host driver
// ---------------------------------------------------------------------------
extern "C" void kernel_launch(void* const* d_in, const int* in_sizes, int n_in,
                              void* d_out, int out_size)
{
    (void)in_sizes; (void)n_in; (void)out_size;

    const float* xc     = (const float*)d_in[0];
    const float* xt     = (const float*)d_in[1];
    const float* enc_Wi = (const float*)d_in[2];
    const float* enc_bi = (const float*)d_in[3];
    const float* enc_td = (const float*)d_in[4];
    const float* enc_Wo = (const float*)d_in[5];
    const float* enc_bo = (const float*)d_in[6];
    const float* enc_g  = (const float*)d_in[7];
    const float* enc_be = (const float*)d_in[8];
    const float* tgt_Wi = (const float*)d_in[9];
    const float* tgt_bi = (const float*)d_in[10];
    const float* tgt_td = (const float*)d_in[11];
    const float* tgt_Wo = (const float*)d_in[12];
    const float* tgt_bo = (const float*)d_in[13];
    const float* tgt_g  = (const float*)d_in[14];
    const float* tgt_be = (const float*)d_in[15];
    const float* gate_W = (const float*)d_in[16];
    const float* gate_b = (const float*)d_in[17];
    const float* lora_A = (const float*)d_in[18];
    const float* lora_B = (const float*)d_in[19];

    float* out = (float*)d_out;
    float* out_pred  = out;
    float* out_probs = out + TDSZ;
    float* out_ztgt  = out + TDSZ + (size_t)T_TOK * NEXP;

    static __nv_bfloat16 *pAh = nullptr, *pAl, *pWh, *pWl;
    static float *pX, *pY, *pH, *pM;
    if (!pAh) {
        cudaGetSymbolAddress((void**)&pAh, g_acth);
        cudaGetSymbolAddress((void**)&pAl, g_actl);
        cudaGetSymbolAddress((void**)&pWh, g_WhT);
        cudaGetSymbolAddress((void**)&pWl, g_WlT);
        cudaGetSymbolAddress((void**)&pX, g_bufX);
        cudaGetSymbolAddress((void**)&pY, g_bufY);
        cudaGetSymbolAddress((void**)&pH, g_h);
        cudaGetSymbolAddress((void**)&pM, g_mask);
        cudaFuncSetAttribute(hgemm<MODE_S>, cudaFuncAttributeMaxDynamicSharedMemorySize, SMEM_TOTAL);
        cudaFuncSetAttribute(hgemm<MODE_Y>, cudaFuncAttributeMaxDynamicSharedMemorySize, SMEM_TOTAL);
    }

    // weight transpose+split: enc Wi->0,2,4 Wo->1,3,5; tgt Wi->6,8,10 Wo->7,9,11
    const dim3 wgrid(32, 32, 3), wblk(32, 8);
    wsplit_kernel<<<wgrid, wblk>>>(enc_Wi, 0, 2, pWh, pWl);
    wsplit_kernel<<<wgrid, wblk>>>(enc_Wo, 1, 2, pWh, pWl);
    wsplit_kernel<<<wgrid, wblk>>>(tgt_Wi, 6, 2, pWh, pWl);
    wsplit_kernel<<<wgrid, wblk>>>(tgt_Wo, 7, 2, pWh, pWl);

    // activation splits into x-slots 0 (enc) and 2 (tgt)
    asplit_kernel<<<(T_TOK * DLAT / 4) / 256, 256>>>(xc, pAh, pAl);
    asplit_kernel<<<(T_TOK * DLAT / 4) / 256, 256>>>(xt, pAh + 2 * TDSZ, pAl + 2 * TDSZ);

    const dim3 ggrid(DLAT / BN, T_TOK / BM, 2);   // (4, 128, 2)
    float* bufX0 = pX;
    float* bufX1 = pX + TDSZ;

    for (int l = 0; l < NLAYER; l++) {
        const size_t vo = (size_t)l * DLAT;
        const float* X0 = l ? bufX0 : xc;
        const float* X1 = l ? bufX1 : xt;

        // GEMM1 (batched): s = sigmoid(x@Wi+bi)*x*td -> act slots 1/3
        hgemm<MODE_S><<<ggrid, 256, SMEM_TOTAL>>>(
            pAh, pAl, pWh, pWl, /*as0=*/0, /*ws0=*/2 * l, /*ws1=*/6 + 2 * l,
            enc_bi + vo, tgt_bi + vo, enc_td + vo, tgt_td + vo,
            X0, X1, nullptr, pAh, pAl);

        // GEMM2 (batched): y = s@Wo + bo + x -> g_bufY slots 0/1
        hgemm<MODE_Y><<<ggrid, 256, SMEM_TOTAL>>>(
            pAh, pAl, pWh, pWl, /*as0=*/1, /*ws0=*/2 * l + 1, /*ws1=*/7 + 2 * l,
            enc_bo + vo, tgt_bo + vo, nullptr, nullptr,
            X0, X1, pY, nullptr, nullptr);

        // LN (batched)
        const int split = (l < NLAYER - 1) ? 1 : 0;
        float* out1 = (l == NLAYER - 1) ? out_ztgt : bufX1;
        ln_kernel<<<dim3(T_TOK, 2), 256>>>(pY, enc_g + vo, tgt_g + vo,
                                           enc_be + vo, tgt_be + vo,
                                           bufX0, out1, pAh, pAl, split);
    }

    // MoLE on z_context (= bufX0)
    gate_kernel<<<T_TOK * 32 / 256, 256>>>(bufX0, gate_W, gate_b, out_probs, pM);
    mole_h_kernel<<<T_TOK / 128, 256>>>(bufX0, lora_A, pM, pH);
    mole_p_kernel<<<dim3(8, 128), 256>>>(pH, lora_B, out_pred);
}

// round 6
// speedup vs baseline: 1.0673x; 1.0673x over previous
#include <cuda_runtime.h>
#include <cuda_bf16.h>
#include <math.h>
#include <stdint.h>

// ---------------------------------------------------------------------------
#define T_TOK 16384
#define DLAT  1024
#define NEXP  4
#define RLORA 16
#define NLAYER 3

#define BM 256
#define BN 128
#define BK 32
#define KITERS (DLAT / BK)            // 32
#define PITCH_B 80                    // bytes per smem row (40 bf16), conflict-free
#define STAGE_ROWS 768                // Ah256 | Al256 | Wh128 | Wl128
#define STAGE_BYTES (STAGE_ROWS * PITCH_B)   // 61440
#define SMEM_TOTAL (2 * STAGE_BYTES)         // 122880

#define MODE_S 0
#define MODE_Y 1

#define TDSZ ((size_t)T_TOK * DLAT)

// ---------------------------------------------------------------------------
// Scratch
// ---------------------------------------------------------------------------
__device__ __nv_bfloat16 g_acth[4 * T_TOK * DLAT];   // slots: 0=enc x,1=enc s,2=tgt x,3=tgt s
__device__ __nv_bfloat16 g_actl[4 * T_TOK * DLAT];
__device__ __nv_bfloat16 g_WhT[12 * DLAT * DLAT];    // [slot][N][K]
__device__ __nv_bfloat16 g_WlT[12 * DLAT * DLAT];
__device__ float g_bufX[2 * T_TOK * DLAT];
__device__ float g_bufY[2 * T_TOK * DLAT];
__device__ float g_h[T_TOK * NEXP * RLORA];
__device__ float g_mask[T_TOK * NEXP];

// ---------------------------------------------------------------------------
// PTX helpers (base sm_80-era features only)
// ---------------------------------------------------------------------------
__device__ __forceinline__ uint32_t smem_to_u32(const void* p) {
    uint32_t a;
    asm("{ .reg .u64 t; cvta.to.shared.u64 t, %1; cvt.u32.u64 %0, t; }" : "=r"(a) : "l"(p));
    return a;
}

__device__ __forceinline__ void cp16(uint32_t dst, const void* src) {
    asm volatile("cp.async.cg.shared.global [%0], [%1], 16;" :: "r"(dst), "l"(src));
}

#define CP_COMMIT() asm volatile("cp.async.commit_group;" ::: "memory")
#define CP_WAIT0()  asm volatile("cp.async.wait_group 0;" ::: "memory")

#define LDSM4(r0, r1, r2, r3, addr) \
    asm volatile("ldmatrix.sync.aligned.m8n8.x4.shared.b16 {%0,%1,%2,%3}, [%4];" \
                 : "=r"(r0), "=r"(r1), "=r"(r2), "=r"(r3) : "r"(addr))

__device__ __forceinline__ void hmma(float* d, const uint32_t* a, const uint32_t* b) {
    asm volatile(
        "mma.sync.aligned.m16n8k16.row.col.f32.bf16.bf16.f32 "
        "{%0,%1,%2,%3}, {%4,%5,%6,%7}, {%8,%9}, {%0,%1,%2,%3};"
        : "+f"(d[0]), "+f"(d[1]), "+f"(d[2]), "+f"(d[3])
        : "r"(a[0]), "r"(a[1]), "r"(a[2]), "r"(a[3]), "r"(b[0]), "r"(b[1]));
}

// ---------------------------------------------------------------------------
// Batched bf16-split HMMA GEMM, 512 threads, BM=256 x BN=128, 2-stage pipe
// acc = Ah*Wh + Ah*Wl + Al*Wh  (Markidis 3-term)
// MODE_S: s = sigmoid(acc+bias)*X*td -> bf16 hi/lo into act slot 1+2z
// MODE_Y: y = acc + bias + X         -> fp32 Cf + z*TDSZ
// ---------------------------------------------------------------------------
template <int MODE>
__global__ __launch_bounds__(512, 1)
void hgemm(const __nv_bfloat16* __restrict__ AhB, const __nv_bfloat16* __restrict__ AlB,
           const __nv_bfloat16* __restrict__ WhB, const __nv_bfloat16* __restrict__ WlB,
           int as0, int ws0, int ws1,
           const float* __restrict__ b0, const float* __restrict__ b1,
           const float* __restrict__ t0, const float* __restrict__ t1,
           const float* __restrict__ X0, const float* __restrict__ X1,
           float* __restrict__ CfB,
           __nv_bfloat16* __restrict__ ChB, __nv_bfloat16* __restrict__ ClB)
{
    extern __shared__ char smem[];
    const uint32_t sb = smem_to_u32(smem);
    const int tid = threadIdx.x;
    const int wid = tid >> 5;
    const int lane = tid & 31;
    const int wm = wid >> 2;        // 0..3 -> M 64-tiles
    const int wn = wid & 3;         // 0..3 -> N 32-tiles
    const int m0 = blockIdx.y * BM;
    const int n0 = blockIdx.x * BN;
    const int z  = blockIdx.z;

    const size_t aoff = (size_t)(as0 + 2 * z) * TDSZ;
    const size_t woff = (size_t)(z ? ws1 : ws0) * DLAT * DLAT;
    const float* bias = z ? b1 : b0;
    const float* td   = z ? t1 : t0;
    const float* X    = z ? X1 : X0;

    // loaders: every thread owns A smem row tid; threads <256 also own W row 512+tid
    const __nv_bfloat16* srcA = (tid < 256)
        ? (AhB + aoff + (size_t)(m0 + tid) * DLAT)
        : (AlB + aoff + (size_t)(m0 + tid - 256) * DLAT);
    const __nv_bfloat16* srcW = (tid < 128)
        ? (WhB + woff + (size_t)(n0 + tid) * DLAT)
        : (WlB + woff + (size_t)(n0 + (tid & 127)) * DLAT);
    const uint32_t dA = sb + tid * PITCH_B;
    const uint32_t dW = sb + (512 + tid) * PITCH_B;
    const bool hasW = tid < 256;

    const int a_row = (lane & 7) + ((lane >> 3) & 1) * 8;
    const int a_k   = ((lane >> 4) & 1) * 8;
    const int b_row = (lane & 7) + ((lane >> 4) & 1) * 8;
    const int b_k   = ((lane >> 3) & 1) * 8;

    float acc[4][4][4];
#pragma unroll
    for (int i = 0; i < 4; i++)
#pragma unroll
        for (int j = 0; j < 4; j++)
#pragma unroll
            for (int q = 0; q < 4; q++) acc[i][j][q] = 0.f;

    // stage 0 load
#pragma unroll
    for (int j = 0; j < 4; j++) cp16(dA + j * 16, srcA + j * 8);
    if (hasW) {
#pragma unroll
        for (int j = 0; j < 4; j++) cp16(dW + j * 16, srcW + j * 8);
    }
    CP_COMMIT();

    for (int it = 0; it < KITERS; it++) {
        CP_WAIT0();          // stage it%2 ready (only its group in flight)
        __syncthreads();     // all warps done reading buffer (it+1)%2 from iter it-1
        if (it + 1 < KITERS) {
            const int k0 = (it + 1) * BK;
            const uint32_t so = ((it + 1) & 1) * STAGE_BYTES;
#pragma unroll
            for (int j = 0; j < 4; j++) cp16(dA + so + j * 16, srcA + k0 + j * 8);
            if (hasW) {
#pragma unroll
                for (int j = 0; j < 4; j++) cp16(dW + so + j * 16, srcW + k0 + j * 8);
            }
            CP_COMMIT();
        }

        const uint32_t st = sb + (it & 1) * STAGE_BYTES;
#pragma unroll
        for (int ko = 0; ko < BK; ko += 16) {
            uint32_t ah[4][4], al[4][4];
#pragma unroll
            for (int mi = 0; mi < 4; mi++) {
                const uint32_t ra = st + (uint32_t)(wm * 64 + mi * 16 + a_row) * PITCH_B
                                       + (uint32_t)(ko + a_k) * 2;
                LDSM4(ah[mi][0], ah[mi][1], ah[mi][2], ah[mi][3], ra);
                LDSM4(al[mi][0], al[mi][1], al[mi][2], al[mi][3], ra + 256 * PITCH_B);
            }
#pragma unroll
            for (int half = 0; half < 2; half++) {
                uint32_t bh[2][2], bl[2][2];
                const uint32_t rb = st + (uint32_t)(512 + wn * 32 + half * 16 + b_row) * PITCH_B
                                       + (uint32_t)(ko + b_k) * 2;
                uint32_t q0, q1, q2, q3;
                LDSM4(q0, q1, q2, q3, rb);
                bh[0][0] = q0; bh[0][1] = q1; bh[1][0] = q2; bh[1][1] = q3;
                LDSM4(q0, q1, q2, q3, rb + 128 * PITCH_B);
                bl[0][0] = q0; bl[0][1] = q1; bl[1][0] = q2; bl[1][1] = q3;
#pragma unroll
                for (int mi = 0; mi < 4; mi++)
#pragma unroll
                    for (int ln = 0; ln < 2; ln++) {
                        float* d = acc[mi][half * 2 + ln];
                        hmma(d, ah[mi], bh[ln]);
                        hmma(d, ah[mi], bl[ln]);
                        hmma(d, al[mi], bh[ln]);
                    }
            }
        }
    }

    // ---------------- epilogue ----------------
    __nv_bfloat16* Ch = ChB + (size_t)(1 + 2 * z) * TDSZ;
    __nv_bfloat16* Cl = ClB + (size_t)(1 + 2 * z) * TDSZ;
    float* Cf = CfB + (size_t)z * TDSZ;

    const int qr = lane >> 2;
    const int qc = (lane & 3) * 2;
#pragma unroll
    for (int mi = 0; mi < 4; mi++) {
#pragma unroll
        for (int ni = 0; ni < 4; ni++) {
            const int r = m0 + wm * 64 + mi * 16 + qr;
            const int c = n0 + wn * 32 + ni * 8 + qc;
            const float* d = acc[mi][ni];
#pragma unroll
            for (int h = 0; h < 2; h++) {
                const int rr = r + h * 8;
                const float v0 = d[2 * h], v1 = d[2 * h + 1];
                const float2 xv = *(const float2*)&X[(size_t)rr * DLAT + c];
                const float2 bv = *(const float2*)&bias[c];
                if (MODE == MODE_S) {
                    const float2 tv = *(const float2*)&td[c];
                    const float s0 = (1.f / (1.f + expf(-(v0 + bv.x)))) * xv.x * tv.x;
                    const float s1v = (1.f / (1.f + expf(-(v1 + bv.y)))) * xv.y * tv.y;
                    const __nv_bfloat16 h0 = __float2bfloat16(s0);
                    const __nv_bfloat16 h1 = __float2bfloat16(s1v);
                    const __nv_bfloat16 l0 = __float2bfloat16(s0 - __bfloat162float(h0));
                    const __nv_bfloat16 l1 = __float2bfloat16(s1v - __bfloat162float(h1));
                    *(__nv_bfloat162*)&Ch[(size_t)rr * DLAT + c] = __nv_bfloat162(h0, h1);
                    *(__nv_bfloat162*)&Cl[(size_t)rr * DLAT + c] = __nv_bfloat162(l0, l1);
                } else {
                    float2 o;
                    o.x = v0 + bv.x + xv.x;
                    o.y = v1 + bv.y + xv.y;
                    *(float2*)&Cf[(size_t)rr * DLAT + c] = o;
                }
            }
        }
    }
}

// ---------------------------------------------------------------------------
// Weight transpose + bf16 split
// ---------------------------------------------------------------------------
__global__ void wsplit_kernel(const float* __restrict__ W, int slot_base, int slot_stride,
                              __nv_bfloat16* __restrict__ WhT, __nv_bfloat16* __restrict__ WlT)
{
    __shared__ float t[32][33];
    const int l = blockIdx.z;
    const float* Wl = W + (size_t)l * DLAT * DLAT;
    const int bx = blockIdx.x * 32;
    const int by = blockIdx.y * 32;
    const int tx = threadIdx.x, ty = threadIdx.y;
#pragma unroll
    for (int i = 0; i < 32; i += 8)
        t[ty + i][tx] = Wl[(size_t)(by + ty + i) * DLAT + bx + tx];
    __syncthreads();
    const size_t slot = (size_t)(slot_base + l * slot_stride) * DLAT * DLAT;
#pragma unroll
    for (int i = 0; i < 32; i += 8) {
        const float v = t[tx][ty + i];
        const __nv_bfloat16 h = __float2bfloat16(v);
        const size_t o = slot + (size_t)(bx + ty + i) * DLAT + by + tx;
        WhT[o] = h;
        WlT[o] = __float2bfloat16(v - __bfloat162float(h));
    }
}

// ---------------------------------------------------------------------------
// Activation split
// ---------------------------------------------------------------------------
__global__ void asplit_kernel(const float* __restrict__ x,
                              __nv_bfloat16* __restrict__ oh, __nv_bfloat16* __restrict__ ol)
{
    const int i = blockIdx.x * blockDim.x + threadIdx.x;
    const float4 v = ((const float4*)x)[i];
    __nv_bfloat16 h0 = __float2bfloat16(v.x), h1 = __float2bfloat16(v.y);
    __nv_bfloat16 h2 = __float2bfloat16(v.z), h3 = __float2bfloat16(v.w);
    __nv_bfloat162* oh2 = (__nv_bfloat162*)oh;
    __nv_bfloat162* ol2 = (__nv_bfloat162*)ol;
    oh2[2 * i]     = __nv_bfloat162(h0, h1);
    oh2[2 * i + 1] = __nv_bfloat162(h2, h3);
    ol2[2 * i]     = __nv_bfloat162(__float2bfloat16(v.x - __bfloat162float(h0)),
                                    __float2bfloat16(v.y - __bfloat162float(h1)));
    ol2[2 * i + 1] = __nv_bfloat162(__float2bfloat16(v.z - __bfloat162float(h2)),
                                    __float2bfloat16(v.w - __bfloat162float(h3)));
}

// ---------------------------------------------------------------------------
// Batched LayerNorm (gridDim.y = stack); optional bf16 hi/lo split output
// ---------------------------------------------------------------------------
__global__ void ln_kernel(const float* __restrict__ Yb,
                          const float* __restrict__ g0, const float* __restrict__ g1,
                          const float* __restrict__ be0, const float* __restrict__ be1,
                          float* __restrict__ out0, float* __restrict__ out1,
                          __nv_bfloat16* __restrict__ ohB, __nv_bfloat16* __restrict__ olB,
                          int split)
{
    __shared__ float sh[18];
    const int row = blockIdx.x;
    const int z   = blockIdx.y;
    const int tid = threadIdx.x;
    const float* yr = Yb + (size_t)z * TDSZ + (size_t)row * DLAT;
    const float* g  = z ? g1 : g0;
    const float* b  = z ? be1 : be0;
    float* out = z ? out1 : out0;

    float4 v = *(const float4*)&yr[tid * 4];
    float s = v.x + v.y + v.z + v.w;
#pragma unroll
    for (int o = 16; o; o >>= 1) s += __shfl_xor_sync(0xffffffffu, s, o);
    if ((tid & 31) == 0) sh[tid >> 5] = s;
    __syncthreads();
    if (tid == 0) {
        float t = 0.f;
        for (int i = 0; i < 8; i++) t += sh[i];
        sh[16] = t * (1.0f / 1024.0f);
    }
    __syncthreads();
    const float mu = sh[16];
    const float dx = v.x - mu, dy = v.y - mu, dz = v.z - mu, dw = v.w - mu;
    float q = dx * dx + dy * dy + dz * dz + dw * dw;
#pragma unroll
    for (int o = 16; o; o >>= 1) q += __shfl_xor_sync(0xffffffffu, q, o);
    if ((tid & 31) == 0) sh[8 + (tid >> 5)] = q;
    __syncthreads();
    if (tid == 0) {
        float t = 0.f;
        for (int i = 0; i < 8; i++) t += sh[8 + i];
        sh[17] = rsqrtf(t * (1.0f / 1024.0f) + 1e-5f);
    }
    __syncthreads();
    const float r = sh[17];

    float4 gv = *(const float4*)&g[tid * 4];
    float4 bv = *(const float4*)&b[tid * 4];
    float4 o4;
    o4.x = dx * r * gv.x + bv.x;
    o4.y = dy * r * gv.y + bv.y;
    o4.z = dz * r * gv.z + bv.z;
    o4.w = dw * r * gv.w + bv.w;
    *(float4*)&out[(size_t)row * DLAT + tid * 4] = o4;

    if (split) {
        __nv_bfloat16* oh = ohB + (size_t)(2 * z) * TDSZ;
        __nv_bfloat16* ol = olB + (size_t)(2 * z) * TDSZ;
        const size_t o = (size_t)row * DLAT + tid * 4;
        __nv_bfloat16 h0 = __float2bfloat16(o4.x), h1 = __float2bfloat16(o4.y);
        __nv_bfloat16 h2 = __float2bfloat16(o4.z), h3 = __float2bfloat16(o4.w);
        *(__nv_bfloat162*)&oh[o]     = __nv_bfloat162(h0, h1);
        *(__nv_bfloat162*)&oh[o + 2] = __nv_bfloat162(h2, h3);
        *(__nv_bfloat162*)&ol[o]     = __nv_bfloat162(__float2bfloat16(o4.x - __bfloat162float(h0)),
                                                      __float2bfloat16(o4.y - __bfloat162float(h1)));
        *(__nv_bfloat162*)&ol[o + 2] = __nv_bfloat162(__float2bfloat16(o4.z - __bfloat162float(h2)),
                                                      __float2bfloat16(o4.w - __bfloat162float(h3)));
    }
}

// ---------------------------------------------------------------------------
// Gate: softmax + top-2 mask
// ---------------------------------------------------------------------------
__global__ void gate_kernel(const float* __restrict__ Z, const float* __restrict__ gw,
                            const float* __restrict__ gb,
                            float* __restrict__ probs_out, float* __restrict__ mask_out)
{
    const int warp = (blockIdx.x * blockDim.x + threadIdx.x) >> 5;
    const int lane = threadIdx.x & 31;
    if (warp >= T_TOK) return;

    float a0 = 0.f, a1 = 0.f, a2 = 0.f, a3 = 0.f;
    const float* zr = Z + (size_t)warp * DLAT;
    for (int d = lane; d < DLAT; d += 32) {
        const float z = zr[d];
        float4 w = *(const float4*)&gw[d * 4];
        a0 = fmaf(z, w.x, a0); a1 = fmaf(z, w.y, a1);
        a2 = fmaf(z, w.z, a2); a3 = fmaf(z, w.w, a3);
    }
#pragma unroll
    for (int o = 16; o; o >>= 1) {
        a0 += __shfl_xor_sync(0xffffffffu, a0, o);
        a1 += __shfl_xor_sync(0xffffffffu, a1, o);
        a2 += __shfl_xor_sync(0xffffffffu, a2, o);
        a3 += __shfl_xor_sync(0xffffffffu, a3, o);
    }
    if (lane == 0) {
        float lg[4] = {a0 + gb[0], a1 + gb[1], a2 + gb[2], a3 + gb[3]};
        float mx = lg[0];
        for (int i = 1; i < 4; i++) mx = fmaxf(mx, lg[i]);
        float p[4], sum = 0.f;
        for (int i = 0; i < 4; i++) { p[i] = expf(lg[i] - mx); sum += p[i]; }
        const float inv = 1.f / sum;
        for (int i = 0; i < 4; i++) p[i] *= inv;
        int i1 = 0;
        for (int i = 1; i < 4; i++) if (p[i] > p[i1]) i1 = i;
        int i2 = -1;
        for (int i = 0; i < 4; i++)
            if (i != i1 && (i2 < 0 || p[i] > p[i2])) i2 = i;
        for (int i = 0; i < 4; i++) {
            probs_out[(size_t)warp * 4 + i] = p[i];
            mask_out[(size_t)warp * 4 + i] = (i == i1 || i == i2) ? 1.f : 0.f;
        }
    }
}

// ---------------------------------------------------------------------------
// MoLE up-proj (SIMT)
// ---------------------------------------------------------------------------
__global__ __launch_bounds__(256)
void mole_h_kernel(const float* __restrict__ Z, const float* __restrict__ lora_A,
                   const float* __restrict__ mask, float* __restrict__ H)
{
    __shared__ float As[16][132];
    __shared__ float Ws[16][64];
    const int tid = threadIdx.x;
    const int m0 = blockIdx.x * 128;
    const int trow = tid >> 4;
    const int tcol = tid & 15;

    float acc[8][4];
#pragma unroll
    for (int i = 0; i < 8; i++)
#pragma unroll
        for (int j = 0; j < 4; j++) acc[i][j] = 0.f;

    const int ar = tid >> 2;
    const int ac4 = tid & 3;

    for (int k0 = 0; k0 < 1024; k0 += 16) {
#pragma unroll
        for (int i = 0; i < 2; i++) {
            const int r = ar + i * 64;
            float4 v = *(const float4*)&Z[(size_t)(m0 + r) * 1024 + k0 + ac4 * 4];
            As[ac4 * 4 + 0][r] = v.x; As[ac4 * 4 + 1][r] = v.y;
            As[ac4 * 4 + 2][r] = v.z; As[ac4 * 4 + 3][r] = v.w;
        }
#pragma unroll
        for (int i = 0; i < 4; i++) {
            const int lin = tid + 256 * i;
            const int k = lin >> 6, n = lin & 63;
            Ws[k][n] = lora_A[(size_t)(n >> 4) * (1024 * 16) + (size_t)(k0 + k) * 16 + (n & 15)];
        }
        __syncthreads();
#pragma unroll
        for (int kk = 0; kk < 16; kk++) {
            float4 a0 = *(const float4*)&As[kk][trow * 8];
            float4 a1 = *(const float4*)&As[kk][trow * 8 + 4];
            float4 b0 = *(const float4*)&Ws[kk][tcol * 4];
            float a[8] = {a0.x, a0.y, a0.z, a0.w, a1.x, a1.y, a1.z, a1.w};
            float b[4] = {b0.x, b0.y, b0.z, b0.w};
#pragma unroll
            for (int i = 0; i < 8; i++)
#pragma unroll
                for (int j = 0; j < 4; j++)
                    acc[i][j] = fmaf(a[i], b[j], acc[i][j]);
        }
        __syncthreads();
    }
#pragma unroll
    for (int i = 0; i < 8; i++) {
        const int m = m0 + trow * 8 + i;
#pragma unroll
        for (int j = 0; j < 4; j++) {
            const int n = tcol * 4 + j;
            const float x = acc[i][j];
            const float hv = 0.5f * x * (1.f + erff(x * 0.70710678118654752f));
            H[(size_t)m * 64 + n] = hv * mask[(size_t)m * 4 + (n >> 4)];
        }
    }
}

// ---------------------------------------------------------------------------
// MoLE down-proj (SIMT)
// ---------------------------------------------------------------------------
__global__ __launch_bounds__(256)
void mole_p_kernel(const float* __restrict__ A, const float* __restrict__ W,
                   float* __restrict__ C)
{
    const int N = 1024;
    __shared__ float As[16][132];
    __shared__ float Ws[16][128];
    const int tid = threadIdx.x;
    const int m0 = blockIdx.y * 128;
    const int n0 = blockIdx.x * 128;
    const int trow = tid >> 4;
    const int tcol = tid & 15;

    float acc[8][8];
#pragma unroll
    for (int i = 0; i < 8; i++)
#pragma unroll
        for (int j = 0; j < 8; j++) acc[i][j] = 0.f;

    const int ar = tid >> 2;
    const int ac4 = tid & 3;
    const int wr = tid >> 5;
    const int wc4 = tid & 31;

    for (int k0 = 0; k0 < 64; k0 += 16) {
#pragma unroll
        for (int i = 0; i < 2; i++) {
            const int r = ar + i * 64;
            float4 v = *(const float4*)&A[(size_t)(m0 + r) * 64 + k0 + ac4 * 4];
            As[ac4 * 4 + 0][r] = v.x; As[ac4 * 4 + 1][r] = v.y;
            As[ac4 * 4 + 2][r] = v.z; As[ac4 * 4 + 3][r] = v.w;
        }
#pragma unroll
        for (int i = 0; i < 2; i++) {
            const int r = wr + i * 8;
            float4 v = *(const float4*)&W[(size_t)(k0 + r) * N + n0 + wc4 * 4];
            *(float4*)&Ws[r][wc4 * 4] = v;
        }
        __syncthreads();
#pragma unroll
        for (int kk = 0; kk < 16; kk++) {
            float4 a0 = *(const float4*)&As[kk][trow * 8];
            float4 a1 = *(const float4*)&As[kk][trow * 8 + 4];
            float4 b0 = *(const float4*)&Ws[kk][tcol * 8];
            float4 b1 = *(const float4*)&Ws[kk][tcol * 8 + 4];
            float a[8] = {a0.x, a0.y, a0.z, a0.w, a1.x, a1.y, a1.z, a1.w};
            float b[8] = {b0.x, b0.y, b0.z, b0.w, b1.x, b1.y, b1.z, b1.w};
#pragma unroll
            for (int i = 0; i < 8; i++)
#pragma unroll
                for (int j = 0; j < 8; j++)
                    acc[i][j] = fmaf(a[i], b[j], acc[i][j]);
        }
        __syncthreads();
    }
#pragma unroll
    for (int i = 0; i < 8; i++) {
        const int m = m0 + trow * 8 + i;
#pragma unroll
        for (int j = 0; j < 8; j++)
            C[(size_t)m * N + tcol * 8 + n0 + j] = acc[i][j];
    }
}

// ---------------------------------------------------------------------------
// Host driver
// ---------------------------------------------------------------------------
extern "C" void kernel_launch(void* const* d_in, const int* in_sizes, int n_in,
                              void* d_out, int out_size)
{
    (void)in_sizes; (void)n_in; (void)out_size;

    const float* xc     = (const float*)d_in[0];
    const float* xt     = (const float*)d_in[1];
    const float* enc_Wi = (const float*)d_in[2];
    const float* enc_bi = (const float*)d_in[3];
    const float* enc_td = (const float*)d_in[4];
    const float* enc_Wo = (const float*)d_in[5];
    const float* enc_bo = (const float*)d_in[6];
    const float* enc_g  = (const float*)d_in[7];
    const float* enc_be = (const float*)d_in[8];
    const float* tgt_Wi = (const float*)d_in[9];
    const float* tgt_bi = (const float*)d_in[10];
    const float* tgt_td = (const float*)d_in[11];
    const float* tgt_Wo = (const float*)d_in[12];
    const float* tgt_bo = (const float*)d_in[13];
    const float* tgt_g  = (const float*)d_in[14];
    const float* tgt_be = (const float*)d_in[15];
    const float* gate_W = (const float*)d_in[16];
    const float* gate_b = (const float*)d_in[17];
    const float* lora_A = (const float*)d_in[18];
    const float* lora_B = (const float*)d_in[19];

    float* out = (float*)d_out;
    float* out_pred  = out;
    float* out_probs = out + TDSZ;
    float* out_ztgt  = out + TDSZ + (size_t)T_TOK * NEXP;

    static __nv_bfloat16 *pAh = nullptr, *pAl, *pWh, *pWl;
    static float *pX, *pY, *pH, *pM;
    if (!pAh) {
        cudaGetSymbolAddress((void**)&pAh, g_acth);
        cudaGetSymbolAddress((void**)&pAl, g_actl);
        cudaGetSymbolAddress((void**)&pWh, g_WhT);
        cudaGetSymbolAddress((void**)&pWl, g_WlT);
        cudaGetSymbolAddress((void**)&pX, g_bufX);
        cudaGetSymbolAddress((void**)&pY, g_bufY);
        cudaGetSymbolAddress((void**)&pH, g_h);
        cudaGetSymbolAddress((void**)&pM, g_mask);
        cudaFuncSetAttribute(hgemm<MODE_S>, cudaFuncAttributeMaxDynamicSharedMemorySize, SMEM_TOTAL);
        cudaFuncSetAttribute(hgemm<MODE_Y>, cudaFuncAttributeMaxDynamicSharedMemorySize, SMEM_TOTAL);
    }

    // weight transpose+split: enc Wi->0,2,4 Wo->1,3,5; tgt Wi->6,8,10 Wo->7,9,11
    const dim3 wgrid(32, 32, 3), wblk(32, 8);
    wsplit_kernel<<<wgrid, wblk>>>(enc_Wi, 0, 2, pWh, pWl);
    wsplit_kernel<<<wgrid, wblk>>>(enc_Wo, 1, 2, pWh, pWl);
    wsplit_kernel<<<wgrid, wblk>>>(tgt_Wi, 6, 2, pWh, pWl);
    wsplit_kernel<<<wgrid, wblk>>>(tgt_Wo, 7, 2, pWh, pWl);

    // activation splits into x-slots 0 (enc) and 2 (tgt)
    asplit_kernel<<<(T_TOK * DLAT / 4) / 256, 256>>>(xc, pAh, pAl);
    asplit_kernel<<<(T_TOK * DLAT / 4) / 256, 256>>>(xt, pAh + 2 * TDSZ, pAl + 2 * TDSZ);

    const dim3 ggrid(DLAT / BN, T_TOK / BM, 2);   // (8, 64, 2)
    float* bufX0 = pX;
    float* bufX1 = pX + TDSZ;

    for (int l = 0; l < NLAYER; l++) {
        const size_t vo = (size_t)l * DLAT;
        const float* X0 = l ? bufX0 : xc;
        const float* X1 = l ? bufX1 : xt;

        // GEMM1 (batched): s = sigmoid(x@Wi+bi)*x*td -> act slots 1/3
        hgemm<MODE_S><<<ggrid, 512, SMEM_TOTAL>>>(
            pAh, pAl, pWh, pWl, /*as0=*/0, /*ws0=*/2 * l, /*ws1=*/6 + 2 * l,
            enc_bi + vo, tgt_bi + vo, enc_td + vo, tgt_td + vo,
            X0, X1, nullptr, pAh, pAl);

        // GEMM2 (batched): y = s@Wo + bo + x -> g_bufY slots 0/1
        hgemm<MODE_Y><<<ggrid, 512, SMEM_TOTAL>>>(
            pAh, pAl, pWh, pWl, /*as0=*/1, /*ws0=*/2 * l + 1, /*ws1=*/7 + 2 * l,
            enc_bo + vo, tgt_bo + vo, nullptr, nullptr,
            X0, X1, pY, nullptr, nullptr);

        // LN (batched)
        const int split = (l < NLAYER - 1) ? 1 : 0;
        float* out1 = (l == NLAYER - 1) ? out_ztgt : bufX1;
        ln_kernel<<<dim3(T_TOK, 2), 256>>>(pY, enc_g + vo, tgt_g + vo,
                                           enc_be + vo, tgt_be + vo,
                                           bufX0, out1, pAh, pAl, split);
    }

    // MoLE on z_context (= bufX0)
    gate_kernel<<<T_TOK * 32 / 256, 256>>>(bufX0, gate_W, gate_b, out_probs, pM);
    mole_h_kernel<<<T_TOK / 128, 256>>>(bufX0, lora_A, pM, pH);
    mole_p_kernel<<<dim3(8, 128), 256>>>(pH, lora_B, out_pred);
}

// round 11
// speedup vs baseline: 1.1671x; 1.0935x over previous
#include <cuda_runtime.h>
#include <cuda_bf16.h>
#include <cuda_fp16.h>
#include <math.h>
#include <stdint.h>

// ---------------------------------------------------------------------------
#define T_TOK 16384
#define DLAT  1024
#define NEXP  4
#define RLORA 16
#define NLAYER 3

#define BM 256
#define BN 128
#define BK 32
#define KITERS (DLAT / BK)            // 32
#define PITCH_B 80                    // bytes per smem row (40 halves), conflict-free
#define STAGE_ROWS 768                // A 512 | W 256
#define STAGE_BYTES (STAGE_ROWS * PITCH_B)   // 61440
#define SMEM_TOTAL (2 * STAGE_BYTES)         // 122880

#define MODE_S 0
#define MODE_Y 1

#define TDSZ ((size_t)T_TOK * DLAT)
#define WSZ  ((size_t)DLAT * DLAT)

// ---------------------------------------------------------------------------
// Scratch.  16-bit activation buffers, slot map:
//   slots 0,1 (bf16): enc x, enc s        slots 2,3 (fp16 reinterpret): tgt x, tgt s
// Weight buffers: g_WhT slots 0-5 = enc bf16 hi; slots 6-11 = tgt fp16 (reinterpret)
//                 g_WlT slots 0-5 = enc bf16 lo
// ---------------------------------------------------------------------------
__device__ __nv_bfloat16 g_acth[4 * T_TOK * DLAT];
__device__ __nv_bfloat16 g_actl[4 * T_TOK * DLAT];
__device__ __nv_bfloat16 g_WhT[12 * DLAT * DLAT];
__device__ __nv_bfloat16 g_WlT[6 * DLAT * DLAT];
__device__ float g_bufX[2 * T_TOK * DLAT];
__device__ float g_bufY[2 * T_TOK * DLAT];
__device__ float g_h[T_TOK * NEXP * RLORA];
__device__ float g_mask[T_TOK * NEXP];

// ---------------------------------------------------------------------------
// PTX helpers
// ---------------------------------------------------------------------------
__device__ __forceinline__ uint32_t smem_to_u32(const void* p) {
    uint32_t a;
    asm("{ .reg .u64 t; cvta.to.shared.u64 t, %1; cvt.u32.u64 %0, t; }" : "=r"(a) : "l"(p));
    return a;
}

__device__ __forceinline__ void cp16(uint32_t dst, const void* src) {
    asm volatile("cp.async.cg.shared.global [%0], [%1], 16;" :: "r"(dst), "l"(src));
}

#define CP_COMMIT() asm volatile("cp.async.commit_group;" ::: "memory")
#define CP_WAIT0()  asm volatile("cp.async.wait_group 0;" ::: "memory")

#define LDSM4(r0, r1, r2, r3, addr) \
    asm volatile("ldmatrix.sync.aligned.m8n8.x4.shared.b16 {%0,%1,%2,%3}, [%4];" \
                 : "=r"(r0), "=r"(r1), "=r"(r2), "=r"(r3) : "r"(addr))

__device__ __forceinline__ void hmma_bf16(float* d, const uint32_t* a, const uint32_t* b) {
    asm volatile(
        "mma.sync.aligned.m16n8k16.row.col.f32.bf16.bf16.f32 "
        "{%0,%1,%2,%3}, {%4,%5,%6,%7}, {%8,%9}, {%0,%1,%2,%3};"
        : "+f"(d[0]), "+f"(d[1]), "+f"(d[2]), "+f"(d[3])
        : "r"(a[0]), "r"(a[1]), "r"(a[2]), "r"(a[3]), "r"(b[0]), "r"(b[1]));
}

__device__ __forceinline__ void hmma_f16(float* d, const uint32_t* a, const uint32_t* b) {
    asm volatile(
        "mma.sync.aligned.m16n8k16.row.col.f32.f16.f16.f32 "
        "{%0,%1,%2,%3}, {%4,%5,%6,%7}, {%8,%9}, {%0,%1,%2,%3};"
        : "+f"(d[0]), "+f"(d[1]), "+f"(d[2]), "+f"(d[3])
        : "r"(a[0]), "r"(a[1]), "r"(a[2]), "r"(a[3]), "r"(b[0]), "r"(b[1]));
}

// ---------------------------------------------------------------------------
// Mixed-precision batched GEMM, 512 threads, BM=256 x BN=128, 2-stage pipe
//  z=0 (encoder): bf16 3-term split  acc = Ah*Wh + Ah*Wl + Al*Wh
//  z=1 (target):  fp16 2-term split  acc = (Ah+Al)*Wh
// MODE_S: s = sigmoid(acc+bias)*X*td -> 16-bit hi/lo into act slot 1 (bf16) / 3 (fp16)
// MODE_Y: y = acc + bias + X         -> fp32 Cf + z*TDSZ
// ---------------------------------------------------------------------------
template <int MODE>
__global__ __launch_bounds__(512, 1)
void hgemm(const void* __restrict__ AhB, const void* __restrict__ AlB,
           const void* __restrict__ WhB, const void* __restrict__ WlB,
           int as0, int ws0, int ws1,
           const float* __restrict__ b0, const float* __restrict__ b1,
           const float* __restrict__ t0, const float* __restrict__ t1,
           const float* __restrict__ X0, const float* __restrict__ X1,
           float* __restrict__ CfB,
           void* __restrict__ ChB, void* __restrict__ ClB)
{
    extern __shared__ char smem[];
    const uint32_t sb = smem_to_u32(smem);
    const int tid = threadIdx.x;
    const int wid = tid >> 5;
    const int lane = tid & 31;
    const int wm = wid >> 2;
    const int wn = wid & 3;
    const int m0 = blockIdx.y * BM;
    const int n0 = blockIdx.x * BN;
    const int z  = blockIdx.z;

    const float* bias = z ? b1 : b0;
    const float* td   = z ? t1 : t0;
    const float* X    = z ? X1 : X0;

    // loader source pointers (byte-based; both elem types are 2B)
    const char* srcA;
    const char* srcW;
    bool hasW;
    if (z == 0) {
        const __nv_bfloat16* Ah = (const __nv_bfloat16*)AhB + (size_t)as0 * TDSZ;
        const __nv_bfloat16* Al = (const __nv_bfloat16*)AlB + (size_t)as0 * TDSZ;
        const __nv_bfloat16* Wh = (const __nv_bfloat16*)WhB + (size_t)ws0 * WSZ;
        const __nv_bfloat16* Wl = (const __nv_bfloat16*)WlB + (size_t)ws0 * WSZ;
        srcA = (const char*)((tid < 256) ? (Ah + (size_t)(m0 + tid) * DLAT)
                                         : (Al + (size_t)(m0 + tid - 256) * DLAT));
        srcW = (const char*)((tid < 128) ? (Wh + (size_t)(n0 + tid) * DLAT)
                                         : (Wl + (size_t)(n0 + (tid & 127)) * DLAT));
        hasW = tid < 256;
    } else {
        const __half* AhF = (const __half*)AhB + (size_t)(2 + as0) * TDSZ;
        const __half* AlF = (const __half*)AlB + (size_t)(2 + as0) * TDSZ;
        const __half* WhF = (const __half*)WhB + (size_t)ws1 * WSZ;
        srcA = (const char*)((tid < 256) ? (AhF + (size_t)(m0 + tid) * DLAT)
                                         : (AlF + (size_t)(m0 + tid - 256) * DLAT));
        srcW = (const char*)(WhF + (size_t)(n0 + (tid & 127)) * DLAT);
        hasW = tid < 128;
    }
    const uint32_t dA = sb + tid * PITCH_B;
    const uint32_t dW = sb + (512 + tid) * PITCH_B;

    const int a_row = (lane & 7) + ((lane >> 3) & 1) * 8;
    const int a_k   = ((lane >> 4) & 1) * 8;
    const int b_row = (lane & 7) + ((lane >> 4) & 1) * 8;
    const int b_k   = ((lane >> 3) & 1) * 8;

    float acc[4][4][4];
#pragma unroll
    for (int i = 0; i < 4; i++)
#pragma unroll
        for (int j = 0; j < 4; j++)
#pragma unroll
            for (int q = 0; q < 4; q++) acc[i][j][q] = 0.f;

    // stage 0 load
#pragma unroll
    for (int j = 0; j < 4; j++) cp16(dA + j * 16, srcA + j * 16);
    if (hasW) {
#pragma unroll
        for (int j = 0; j < 4; j++) cp16(dW + j * 16, srcW + j * 16);
    }
    CP_COMMIT();

    for (int it = 0; it < KITERS; it++) {
        CP_WAIT0();
        __syncthreads();
        if (it + 1 < KITERS) {
            const int kb = (it + 1) * BK * 2;     // byte offset
            const uint32_t so = ((it + 1) & 1) * STAGE_BYTES;
#pragma unroll
            for (int j = 0; j < 4; j++) cp16(dA + so + j * 16, srcA + kb + j * 16);
            if (hasW) {
#pragma unroll
                for (int j = 0; j < 4; j++) cp16(dW + so + j * 16, srcW + kb + j * 16);
            }
            CP_COMMIT();
        }

        const uint32_t st = sb + (it & 1) * STAGE_BYTES;
        if (z == 0) {
            // ----- bf16 3-term -----
#pragma unroll
            for (int ko = 0; ko < BK; ko += 16) {
                uint32_t ah[4][4], al[4][4];
#pragma unroll
                for (int mi = 0; mi < 4; mi++) {
                    const uint32_t ra = st + (uint32_t)(wm * 64 + mi * 16 + a_row) * PITCH_B
                                           + (uint32_t)(ko + a_k) * 2;
                    LDSM4(ah[mi][0], ah[mi][1], ah[mi][2], ah[mi][3], ra);
                    LDSM4(al[mi][0], al[mi][1], al[mi][2], al[mi][3], ra + 256 * PITCH_B);
                }
#pragma unroll
                for (int half = 0; half < 2; half++) {
                    uint32_t bh[2][2], bl[2][2];
                    const uint32_t rb = st + (uint32_t)(512 + wn * 32 + half * 16 + b_row) * PITCH_B
                                           + (uint32_t)(ko + b_k) * 2;
                    uint32_t q0, q1, q2, q3;
                    LDSM4(q0, q1, q2, q3, rb);
                    bh[0][0] = q0; bh[0][1] = q1; bh[1][0] = q2; bh[1][1] = q3;
                    LDSM4(q0, q1, q2, q3, rb + 128 * PITCH_B);
                    bl[0][0] = q0; bl[0][1] = q1; bl[1][0] = q2; bl[1][1] = q3;
#pragma unroll
                    for (int mi = 0; mi < 4; mi++)
#pragma unroll
                        for (int ln = 0; ln < 2; ln++) {
                            float* d = acc[mi][half * 2 + ln];
                            hmma_bf16(d, ah[mi], bh[ln]);
                            hmma_bf16(d, ah[mi], bl[ln]);
                            hmma_bf16(d, al[mi], bh[ln]);
                        }
                }
            }
        } else {
            // ----- fp16 2-term -----
#pragma unroll
            for (int ko = 0; ko < BK; ko += 16) {
                uint32_t ah[4][4], al[4][4];
#pragma unroll
                for (int mi = 0; mi < 4; mi++) {
                    const uint32_t ra = st + (uint32_t)(wm * 64 + mi * 16 + a_row) * PITCH_B
                                           + (uint32_t)(ko + a_k) * 2;
                    LDSM4(ah[mi][0], ah[mi][1], ah[mi][2], ah[mi][3], ra);
                    LDSM4(al[mi][0], al[mi][1], al[mi][2], al[mi][3], ra + 256 * PITCH_B);
                }
#pragma unroll
                for (int half = 0; half < 2; half++) {
                    uint32_t bh[2][2];
                    const uint32_t rb = st + (uint32_t)(512 + wn * 32 + half * 16 + b_row) * PITCH_B
                                           + (uint32_t)(ko + b_k) * 2;
                    uint32_t q0, q1, q2, q3;
                    LDSM4(q0, q1, q2, q3, rb);
                    bh[0][0] = q0; bh[0][1] = q1; bh[1][0] = q2; bh[1][1] = q3;
#pragma unroll
                    for (int mi = 0; mi < 4; mi++)
#pragma unroll
                        for (int ln = 0; ln < 2; ln++) {
                            float* d = acc[mi][half * 2 + ln];
                            hmma_f16(d, ah[mi], bh[ln]);
                            hmma_f16(d, al[mi], bh[ln]);
                        }
                }
            }
        }
    }

    // ---------------- epilogue ----------------
    float* Cf = CfB + (size_t)z * TDSZ;
    const int qr = lane >> 2;
    const int qc = (lane & 3) * 2;
#pragma unroll
    for (int mi = 0; mi < 4; mi++) {
#pragma unroll
        for (int ni = 0; ni < 4; ni++) {
            const int r = m0 + wm * 64 + mi * 16 + qr;
            const int c = n0 + wn * 32 + ni * 8 + qc;
            const float* d = acc[mi][ni];
#pragma unroll
            for (int h = 0; h < 2; h++) {
                const int rr = r + h * 8;
                const float v0 = d[2 * h], v1 = d[2 * h + 1];
                const float2 xv = *(const float2*)&X[(size_t)rr * DLAT + c];
                const float2 bv = *(const float2*)&bias[c];
                if (MODE == MODE_S) {
                    const float2 tv = *(const float2*)&td[c];
                    const float s0 = (1.f / (1.f + expf(-(v0 + bv.x)))) * xv.x * tv.x;
                    const float s1v = (1.f / (1.f + expf(-(v1 + bv.y)))) * xv.y * tv.y;
                    const size_t o = (size_t)rr * DLAT + c;
                    if (z == 0) {
                        __nv_bfloat16* Ch = (__nv_bfloat16*)ChB + TDSZ;   // slot 1
                        __nv_bfloat16* Cl = (__nv_bfloat16*)ClB + TDSZ;
                        const __nv_bfloat16 h0 = __float2bfloat16(s0);
                        const __nv_bfloat16 h1 = __float2bfloat16(s1v);
                        *(__nv_bfloat162*)&Ch[o] = __nv_bfloat162(h0, h1);
                        *(__nv_bfloat162*)&Cl[o] = __nv_bfloat162(
                            __float2bfloat16(s0 - __bfloat162float(h0)),
                            __float2bfloat16(s1v - __bfloat162float(h1)));
                    } else {
                        __half* Ch = (__half*)ChB + 3 * TDSZ;             // slot 3
                        __half* Cl = (__half*)ClB + 3 * TDSZ;
                        const __half h0 = __float2half(s0);
                        const __half h1 = __float2half(s1v);
                        *(__half2*)&Ch[o] = __half2(h0, h1);
                        *(__half2*)&Cl[o] = __half2(__float2half(s0 - __half2float(h0)),
                                                    __float2half(s1v - __half2float(h1)));
                    }
                } else {
                    float2 o2;
                    o2.x = v0 + bv.x + xv.x;
                    o2.y = v1 + bv.y + xv.y;
                    *(float2*)&Cf[(size_t)rr * DLAT + c] = o2;
                }
            }
        }
    }
}

// ---------------------------------------------------------------------------
// Weight transpose + bf16 hi/lo split (encoder)
// ---------------------------------------------------------------------------
__global__ void wsplit_kernel(const float* __restrict__ W, int slot_base, int slot_stride,
                              __nv_bfloat16* __restrict__ WhT, __nv_bfloat16* __restrict__ WlT)
{
    __shared__ float t[32][33];
    const int l = blockIdx.z;
    const float* Wl = W + (size_t)l * WSZ;
    const int bx = blockIdx.x * 32;
    const int by = blockIdx.y * 32;
    const int tx = threadIdx.x, ty = threadIdx.y;
#pragma unroll
    for (int i = 0; i < 32; i += 8)
        t[ty + i][tx] = Wl[(size_t)(by + ty + i) * DLAT + bx + tx];
    __syncthreads();
    const size_t slot = (size_t)(slot_base + l * slot_stride) * WSZ;
#pragma unroll
    for (int i = 0; i < 32; i += 8) {
        const float v = t[tx][ty + i];
        const __nv_bfloat16 h = __float2bfloat16(v);
        const size_t o = slot + (size_t)(bx + ty + i) * DLAT + by + tx;
        WhT[o] = h;
        WlT[o] = __float2bfloat16(v - __bfloat162float(h));
    }
}

// ---------------------------------------------------------------------------
// Weight transpose + fp16 round only (target)
// ---------------------------------------------------------------------------
__global__ void wsplit_f16_kernel(const float* __restrict__ W, int slot_base, int slot_stride,
                                  __half* __restrict__ WhT)
{
    __shared__ float t[32][33];
    const int l = blockIdx.z;
    const float* Wl = W + (size_t)l * WSZ;
    const int bx = blockIdx.x * 32;
    const int by = blockIdx.y * 32;
    const int tx = threadIdx.x, ty = threadIdx.y;
#pragma unroll
    for (int i = 0; i < 32; i += 8)
        t[ty + i][tx] = Wl[(size_t)(by + ty + i) * DLAT + bx + tx];
    __syncthreads();
    const size_t slot = (size_t)(slot_base + l * slot_stride) * WSZ;
#pragma unroll
    for (int i = 0; i < 32; i += 8)
        WhT[slot + (size_t)(bx + ty + i) * DLAT + by + tx] = __float2half(t[tx][ty + i]);
}

// ---------------------------------------------------------------------------
// Activation splits
// ---------------------------------------------------------------------------
__global__ void asplit_kernel(const float* __restrict__ x,
                              __nv_bfloat16* __restrict__ oh, __nv_bfloat16* __restrict__ ol)
{
    const int i = blockIdx.x * blockDim.x + threadIdx.x;
    const float4 v = ((const float4*)x)[i];
    __nv_bfloat16 h0 = __float2bfloat16(v.x), h1 = __float2bfloat16(v.y);
    __nv_bfloat16 h2 = __float2bfloat16(v.z), h3 = __float2bfloat16(v.w);
    __nv_bfloat162* oh2 = (__nv_bfloat162*)oh;
    __nv_bfloat162* ol2 = (__nv_bfloat162*)ol;
    oh2[2 * i]     = __nv_bfloat162(h0, h1);
    oh2[2 * i + 1] = __nv_bfloat162(h2, h3);
    ol2[2 * i]     = __nv_bfloat162(__float2bfloat16(v.x - __bfloat162float(h0)),
                                    __float2bfloat16(v.y - __bfloat162float(h1)));
    ol2[2 * i + 1] = __nv_bfloat162(__float2bfloat16(v.z - __bfloat162float(h2)),
                                    __float2bfloat16(v.w - __bfloat162float(h3)));
}

__global__ void asplit_f16_kernel(const float* __restrict__ x,
                                  __half* __restrict__ oh, __half* __restrict__ ol)
{
    const int i = blockIdx.x * blockDim.x + threadIdx.x;
    const float4 v = ((const float4*)x)[i];
    __half h0 = __float2half(v.x), h1 = __float2half(v.y);
    __half h2 = __float2half(v.z), h3 = __float2half(v.w);
    __half2* oh2 = (__half2*)oh;
    __half2* ol2 = (__half2*)ol;
    oh2[2 * i]     = __half2(h0, h1);
    oh2[2 * i + 1] = __half2(h2, h3);
    ol2[2 * i]     = __half2(__float2half(v.x - __half2float(h0)),
                             __float2half(v.y - __half2float(h1)));
    ol2[2 * i + 1] = __half2(__float2half(v.z - __half2float(h2)),
                             __float2half(v.w - __half2float(h3)));
}

// ---------------------------------------------------------------------------
// Batched LayerNorm; split output bf16 (z=0, slot0) or fp16 (z=1, slot2)
// ---------------------------------------------------------------------------
__global__ void ln_kernel(const float* __restrict__ Yb,
                          const float* __restrict__ g0, const float* __restrict__ g1,
                          const float* __restrict__ be0, const float* __restrict__ be1,
                          float* __restrict__ out0, float* __restrict__ out1,
                          void* __restrict__ ohB, void* __restrict__ olB,
                          int split)
{
    __shared__ float sh[18];
    const int row = blockIdx.x;
    const int z   = blockIdx.y;
    const int tid = threadIdx.x;
    const float* yr = Yb + (size_t)z * TDSZ + (size_t)row * DLAT;
    const float* g  = z ? g1 : g0;
    const float* b  = z ? be1 : be0;
    float* out = z ? out1 : out0;

    float4 v = *(const float4*)&yr[tid * 4];
    float s = v.x + v.y + v.z + v.w;
#pragma unroll
    for (int o = 16; o; o >>= 1) s += __shfl_xor_sync(0xffffffffu, s, o);
    if ((tid & 31) == 0) sh[tid >> 5] = s;
    __syncthreads();
    if (tid == 0) {
        float t = 0.f;
        for (int i = 0; i < 8; i++) t += sh[i];
        sh[16] = t * (1.0f / 1024.0f);
    }
    __syncthreads();
    const float mu = sh[16];
    const float dx = v.x - mu, dy = v.y - mu, dz = v.z - mu, dw = v.w - mu;
    float q = dx * dx + dy * dy + dz * dz + dw * dw;
#pragma unroll
    for (int o = 16; o; o >>= 1) q += __shfl_xor_sync(0xffffffffu, q, o);
    if ((tid & 31) == 0) sh[8 + (tid >> 5)] = q;
    __syncthreads();
    if (tid == 0) {
        float t = 0.f;
        for (int i = 0; i < 8; i++) t += sh[8 + i];
        sh[17] = rsqrtf(t * (1.0f / 1024.0f) + 1e-5f);
    }
    __syncthreads();
    const float r = sh[17];

    float4 gv = *(const float4*)&g[tid * 4];
    float4 bv = *(const float4*)&b[tid * 4];
    float4 o4;
    o4.x = dx * r * gv.x + bv.x;
    o4.y = dy * r * gv.y + bv.y;
    o4.z = dz * r * gv.z + bv.z;
    o4.w = dw * r * gv.w + bv.w;
    *(float4*)&out[(size_t)row * DLAT + tid * 4] = o4;

    if (split) {
        const size_t o = (size_t)row * DLAT + tid * 4;
        if (z == 0) {
            __nv_bfloat16* oh = (__nv_bfloat16*)ohB;          // slot 0
            __nv_bfloat16* ol = (__nv_bfloat16*)olB;
            __nv_bfloat16 h0 = __float2bfloat16(o4.x), h1 = __float2bfloat16(o4.y);
            __nv_bfloat16 h2 = __float2bfloat16(o4.z), h3 = __float2bfloat16(o4.w);
            *(__nv_bfloat162*)&oh[o]     = __nv_bfloat162(h0, h1);
            *(__nv_bfloat162*)&oh[o + 2] = __nv_bfloat162(h2, h3);
            *(__nv_bfloat162*)&ol[o]     = __nv_bfloat162(__float2bfloat16(o4.x - __bfloat162float(h0)),
                                                          __float2bfloat16(o4.y - __bfloat162float(h1)));
            *(__nv_bfloat162*)&ol[o + 2] = __nv_bfloat162(__float2bfloat16(o4.z - __bfloat162float(h2)),
                                                          __float2bfloat16(o4.w - __bfloat162float(h3)));
        } else {
            __half* oh = (__half*)ohB + 2 * TDSZ;             // slot 2
            __half* ol = (__half*)olB + 2 * TDSZ;
            __half h0 = __float2half(o4.x), h1 = __float2half(o4.y);
            __half h2 = __float2half(o4.z), h3 = __float2half(o4.w);
            *(__half2*)&oh[o]     = __half2(h0, h1);
            *(__half2*)&oh[o + 2] = __half2(h2, h3);
            *(__half2*)&ol[o]     = __half2(__float2half(o4.x - __half2float(h0)),
                                            __float2half(o4.y - __half2float(h1)));
            *(__half2*)&ol[o + 2] = __half2(__float2half(o4.z - __half2float(h2)),
                                            __float2half(o4.w - __half2float(h3)));
        }
    }
}

// ---------------------------------------------------------------------------
// Gate: softmax + top-2 mask
// ---------------------------------------------------------------------------
__global__ void gate_kernel(const float* __restrict__ Z, const float* __restrict__ gw,
                            const float* __restrict__ gb,
                            float* __restrict__ probs_out, float* __restrict__ mask_out)
{
    const int warp = (blockIdx.x * blockDim.x + threadIdx.x) >> 5;
    const int lane = threadIdx.x & 31;
    if (warp >= T_TOK) return;

    float a0 = 0.f, a1 = 0.f, a2 = 0.f, a3 = 0.f;
    const float* zr = Z + (size_t)warp * DLAT;
    for (int d = lane; d < DLAT; d += 32) {
        const float z = zr[d];
        float4 w = *(const float4*)&gw[d * 4];
        a0 = fmaf(z, w.x, a0); a1 = fmaf(z, w.y, a1);
        a2 = fmaf(z, w.z, a2); a3 = fmaf(z, w.w, a3);
    }
#pragma unroll
    for (int o = 16; o; o >>= 1) {
        a0 += __shfl_xor_sync(0xffffffffu, a0, o);
        a1 += __shfl_xor_sync(0xffffffffu, a1, o);
        a2 += __shfl_xor_sync(0xffffffffu, a2, o);
        a3 += __shfl_xor_sync(0xffffffffu, a3, o);
    }
    if (lane == 0) {
        float lg[4] = {a0 + gb[0], a1 + gb[1], a2 + gb[2], a3 + gb[3]};
        float mx = lg[0];
        for (int i = 1; i < 4; i++) mx = fmaxf(mx, lg[i]);
        float p[4], sum = 0.f;
        for (int i = 0; i < 4; i++) { p[i] = expf(lg[i] - mx); sum += p[i]; }
        const float inv = 1.f / sum;
        for (int i = 0; i < 4; i++) p[i] *= inv;
        int i1 = 0;
        for (int i = 1; i < 4; i++) if (p[i] > p[i1]) i1 = i;
        int i2 = -1;
        for (int i = 0; i < 4; i++)
            if (i != i1 && (i2 < 0 || p[i] > p[i2])) i2 = i;
        for (int i = 0; i < 4; i++) {
            probs_out[(size_t)warp * 4 + i] = p[i];
            mask_out[(size_t)warp * 4 + i] = (i == i1 || i == i2) ? 1.f : 0.f;
        }
    }
}

// ---------------------------------------------------------------------------
// MoLE up-proj (SIMT)
// ---------------------------------------------------------------------------
__global__ __launch_bounds__(256)
void mole_h_kernel(const float* __restrict__ Z, const float* __restrict__ lora_A,
                   const float* __restrict__ mask, float* __restrict__ H)
{
    __shared__ float As[16][132];
    __shared__ float Ws[16][64];
    const int tid = threadIdx.x;
    const int m0 = blockIdx.x * 128;
    const int trow = tid >> 4;
    const int tcol = tid & 15;

    float acc[8][4];
#pragma unroll
    for (int i = 0; i < 8; i++)
#pragma unroll
        for (int j = 0; j < 4; j++) acc[i][j] = 0.f;

    const int ar = tid >> 2;
    const int ac4 = tid & 3;

    for (int k0 = 0; k0 < 1024; k0 += 16) {
#pragma unroll
        for (int i = 0; i < 2; i++) {
            const int r = ar + i * 64;
            float4 v = *(const float4*)&Z[(size_t)(m0 + r) * 1024 + k0 + ac4 * 4];
            As[ac4 * 4 + 0][r] = v.x; As[ac4 * 4 + 1][r] = v.y;
            As[ac4 * 4 + 2][r] = v.z; As[ac4 * 4 + 3][r] = v.w;
        }
#pragma unroll
        for (int i = 0; i < 4; i++) {
            const int lin = tid + 256 * i;
            const int k = lin >> 6, n = lin & 63;
            Ws[k][n] = lora_A[(size_t)(n >> 4) * (1024 * 16) + (size_t)(k0 + k) * 16 + (n & 15)];
        }
        __syncthreads();
#pragma unroll
        for (int kk = 0; kk < 16; kk++) {
            float4 a0 = *(const float4*)&As[kk][trow * 8];
            float4 a1 = *(const float4*)&As[kk][trow * 8 + 4];
            float4 b0 = *(const float4*)&Ws[kk][tcol * 4];
            float a[8] = {a0.x, a0.y, a0.z, a0.w, a1.x, a1.y, a1.z, a1.w};
            float b[4] = {b0.x, b0.y, b0.z, b0.w};
#pragma unroll
            for (int i = 0; i < 8; i++)
#pragma unroll
                for (int j = 0; j < 4; j++)
                    acc[i][j] = fmaf(a[i], b[j], acc[i][j]);
        }
        __syncthreads();
    }
#pragma unroll
    for (int i = 0; i < 8; i++) {
        const int m = m0 + trow * 8 + i;
#pragma unroll
        for (int j = 0; j < 4; j++) {
            const int n = tcol * 4 + j;
            const float x = acc[i][j];
            const float hv = 0.5f * x * (1.f + erff(x * 0.70710678118654752f));
            H[(size_t)m * 64 + n] = hv * mask[(size_t)m * 4 + (n >> 4)];
        }
    }
}

// ---------------------------------------------------------------------------
// MoLE down-proj (SIMT)
// ---------------------------------------------------------------------------
__global__ __launch_bounds__(256)
void mole_p_kernel(const float* __restrict__ A, const float* __restrict__ W,
                   float* __restrict__ C)
{
    const int N = 1024;
    __shared__ float As[16][132];
    __shared__ float Ws[16][128];
    const int tid = threadIdx.x;
    const int m0 = blockIdx.y * 128;
    const int n0 = blockIdx.x * 128;
    const int trow = tid >> 4;
    const int tcol = tid & 15;

    float acc[8][8];
#pragma unroll
    for (int i = 0; i < 8; i++)
#pragma unroll
        for (int j = 0; j < 8; j++) acc[i][j] = 0.f;

    const int ar = tid >> 2;
    const int ac4 = tid & 3;
    const int wr = tid >> 5;
    const int wc4 = tid & 31;

    for (int k0 = 0; k0 < 64; k0 += 16) {
#pragma unroll
        for (int i = 0; i < 2; i++) {
            const int r = ar + i * 64;
            float4 v = *(const float4*)&A[(size_t)(m0 + r) * 64 + k0 + ac4 * 4];
            As[ac4 * 4 + 0][r] = v.x; As[ac4 * 4 + 1][r] = v.y;
            As[ac4 * 4 + 2][r] = v.z; As[ac4 * 4 + 3][r] = v.w;
        }
#pragma unroll
        for (int i = 0; i < 2; i++) {
            const int r = wr + i * 8;
            float4 v = *(const float4*)&W[(size_t)(k0 + r) * N + n0 + wc4 * 4];
            *(float4*)&Ws[r][wc4 * 4] = v;
        }
        __syncthreads();
#pragma unroll
        for (int kk = 0; kk < 16; kk++) {
            float4 a0 = *(const float4*)&As[kk][trow * 8];
            float4 a1 = *(const float4*)&As[kk][trow * 8 + 4];
            float4 b0 = *(const float4*)&Ws[kk][tcol * 8];
            float4 b1 = *(const float4*)&Ws[kk][tcol * 8 + 4];
            float a[8] = {a0.x, a0.y, a0.z, a0.w, a1.x, a1.y, a1.z, a1.w};
            float b[8] = {b0.x, b0.y, b0.z, b0.w, b1.x, b1.y, b1.z, b1.w};
#pragma unroll
            for (int i = 0; i < 8; i++)
#pragma unroll
                for (int j = 0; j < 8; j++)
                    acc[i][j] = fmaf(a[i], b[j], acc[i][j]);
        }
        __syncthreads();
    }
#pragma unroll
    for (int i = 0; i < 8; i++) {
        const int m = m0 + trow * 8 + i;
#pragma unroll
        for (int j = 0; j < 8; j++)
            C[(size_t)m * N + tcol * 8 + n0 + j] = acc[i][j];
    }
}

// ---------------------------------------------------------------------------
// Host driver
// ---------------------------------------------------------------------------
extern "C" void kernel_launch(void* const* d_in, const int* in_sizes, int n_in,
                              void* d_out, int out_size)
{
    (void)in_sizes; (void)n_in; (void)out_size;

    const float* xc     = (const float*)d_in[0];
    const float* xt     = (const float*)d_in[1];
    const float* enc_Wi = (const float*)d_in[2];
    const float* enc_bi = (const float*)d_in[3];
    const float* enc_td = (const float*)d_in[4];
    const float* enc_Wo = (const float*)d_in[5];
    const float* enc_bo = (const float*)d_in[6];
    const float* enc_g  = (const float*)d_in[7];
    const float* enc_be = (const float*)d_in[8];
    const float* tgt_Wi = (const float*)d_in[9];
    const float* tgt_bi = (const float*)d_in[10];
    const float* tgt_td = (const float*)d_in[11];
    const float* tgt_Wo = (const float*)d_in[12];
    const float* tgt_bo = (const float*)d_in[13];
    const float* tgt_g  = (const float*)d_in[14];
    const float* tgt_be = (const float*)d_in[15];
    const float* gate_W = (const float*)d_in[16];
    const float* gate_b = (const float*)d_in[17];
    const float* lora_A = (const float*)d_in[18];
    const float* lora_B = (const float*)d_in[19];

    float* out = (float*)d_out;
    float* out_pred  = out;
    float* out_probs = out + TDSZ;
    float* out_ztgt  = out + TDSZ + (size_t)T_TOK * NEXP;

    static __nv_bfloat16 *pAh = nullptr, *pAl, *pWh;
    static __nv_bfloat16 *pWl;
    static float *pX, *pY, *pH, *pM;
    if (!pAh) {
        cudaGetSymbolAddress((void**)&pAh, g_acth);
        cudaGetSymbolAddress((void**)&pAl, g_actl);
        cudaGetSymbolAddress((void**)&pWh, g_WhT);
        cudaGetSymbolAddress((void**)&pWl, g_WlT);
        cudaGetSymbolAddress((void**)&pX, g_bufX);
        cudaGetSymbolAddress((void**)&pY, g_bufY);
        cudaGetSymbolAddress((void**)&pH, g_h);
        cudaGetSymbolAddress((void**)&pM, g_mask);
        cudaFuncSetAttribute(hgemm<MODE_S>, cudaFuncAttributeMaxDynamicSharedMemorySize, SMEM_TOTAL);
        cudaFuncSetAttribute(hgemm<MODE_Y>, cudaFuncAttributeMaxDynamicSharedMemorySize, SMEM_TOTAL);
    }

    // weights: enc (bf16 split) Wi->0,2,4 Wo->1,3,5; tgt (fp16) Wi->6,8,10 Wo->7,9,11
    const dim3 wgrid(32, 32, 3), wblk(32, 8);
    wsplit_kernel<<<wgrid, wblk>>>(enc_Wi, 0, 2, pWh, pWl);
    wsplit_kernel<<<wgrid, wblk>>>(enc_Wo, 1, 2, pWh, pWl);
    wsplit_f16_kernel<<<wgrid, wblk>>>(tgt_Wi, 6, 2, (__half*)pWh);
    wsplit_f16_kernel<<<wgrid, wblk>>>(tgt_Wo, 7, 2, (__half*)pWh);

    // activation splits: enc bf16 -> slot 0; tgt fp16 -> slot 2
    asplit_kernel<<<(T_TOK * DLAT / 4) / 256, 256>>>(xc, pAh, pAl);
    asplit_f16_kernel<<<(T_TOK * DLAT / 4) / 256, 256>>>(
        xt, (__half*)pAh + 2 * TDSZ, (__half*)pAl + 2 * TDSZ);

    const dim3 ggrid(DLAT / BN, T_TOK / BM, 2);   // (8, 64, 2)
    float* bufX0 = pX;
    float* bufX1 = pX + TDSZ;

    for (int l = 0; l < NLAYER; l++) {
        const size_t vo = (size_t)l * DLAT;
        const float* X0 = l ? bufX0 : xc;
        const float* X1 = l ? bufX1 : xt;

        // GEMM1: s = sigmoid(x@Wi+bi)*x*td -> act slots 1 (bf16) / 3 (fp16)
        hgemm<MODE_S><<<ggrid, 512, SMEM_TOTAL>>>(
            pAh, pAl, pWh, pWl, /*as0=*/0, /*ws0=*/2 * l, /*ws1=*/6 + 2 * l,
            enc_bi + vo, tgt_bi + vo, enc_td + vo, tgt_td + vo,
            X0, X1, nullptr, pAh, pAl);

        // GEMM2: y = s@Wo + bo + x -> g_bufY slots 0/1
        hgemm<MODE_Y><<<ggrid, 512, SMEM_TOTAL>>>(
            pAh, pAl, pWh, pWl, /*as0=*/1, /*ws0=*/2 * l + 1, /*ws1=*/7 + 2 * l,
            enc_bo + vo, tgt_bo + vo, nullptr, nullptr,
            X0, X1, pY, nullptr, nullptr);

        // LN (batched)
        const int split = (l < NLAYER - 1) ? 1 : 0;
        float* out1 = (l == NLAYER - 1) ? out_ztgt : bufX1;
        ln_kernel<<<dim3(T_TOK, 2), 256>>>(pY, enc_g + vo, tgt_g + vo,
                                           enc_be + vo, tgt_be + vo,
                                           bufX0, out1, pAh, pAl, split);
    }

    // MoLE on z_context (= bufX0)
    gate_kernel<<<T_TOK * 32 / 256, 256>>>(bufX0, gate_W, gate_b, out_probs, pM);
    mole_h_kernel<<<T_TOK / 128, 256>>>(bufX0, lora_A, pM, pH);
    mole_p_kernel<<<dim3(8, 128), 256>>>(pH, lora_B, out_pred);
}